// round 4
// baseline (speedup 1.0000x reference)
#include <cuda_runtime.h>

// Problem constants (fixed by the dataset)
#define kN 100000
#define kE 1600000
#define kG 256
// HID = 128 features = 32 float4 per row

// ---------------- scratch (static device allocations; no cudaMalloc) ----------
__device__ float4 g_agg[kN * 32];   // 51.2 MB  edge-sum accumulator
__device__ float4 g_h1 [kN * 32];   // 51.2 MB  layer-1 activations
__device__ int    g_deg[kN];
__device__ float  g_deginv[kN];
__device__ int    g_gcnt[kG];
__device__ float  g_gacc[kG];

// ---------------- f32x2 packed-math helpers (Blackwell) -----------------------
__device__ __forceinline__ unsigned long long pack2(float a, float b) {
    unsigned long long r;
    asm("mov.b64 %0, {%1, %2};" : "=l"(r) : "f"(a), "f"(b));
    return r;
}
__device__ __forceinline__ void unpack2(unsigned long long v, float &a, float &b) {
    asm("mov.b64 {%0, %1}, %2;" : "=f"(a), "=f"(b) : "l"(v));
}
__device__ __forceinline__ unsigned long long fma2(unsigned long long a,
                                                   unsigned long long b,
                                                   unsigned long long c) {
    unsigned long long d;
    asm("fma.rn.f32x2 %0, %1, %2, %3;" : "=l"(d) : "l"(a), "l"(b), "l"(c));
    return d;
}

// ---------------- tiny utility kernels ----------------------------------------
__global__ void k_zero_agg() {
    int i = blockIdx.x * blockDim.x + threadIdx.x;
    int stride = gridDim.x * blockDim.x;
    float4 z = make_float4(0.f, 0.f, 0.f, 0.f);
    for (; i < kN * 32; i += stride) g_agg[i] = z;
}

__global__ void k_zero_misc() {
    int i = blockIdx.x * blockDim.x + threadIdx.x;
    int stride = gridDim.x * blockDim.x;
    for (int j = i; j < kN; j += stride) g_deg[j] = 0;
    if (i < kG) { g_gcnt[i] = 0; g_gacc[i] = 0.f; }
}

// NOTE: edge_index / batch are int32 on the wire (JAX default x64-disabled
// silently downcasts the reference's jnp.int64 request).
__global__ void k_count(const int* __restrict__ ei,
                        const int* __restrict__ batch) {
    int t = blockIdx.x * blockDim.x + threadIdx.x;
    int stride = gridDim.x * blockDim.x;
    const int* dstp = ei + kE;
    for (int e = t; e < kE; e += stride) atomicAdd(&g_deg[dstp[e]], 1);
    for (int i = t; i < kN; i += stride) atomicAdd(&g_gcnt[batch[i]], 1);
}

__global__ void k_deginv() {
    int t = blockIdx.x * blockDim.x + threadIdx.x;
    for (int i = t; i < kN; i += gridDim.x * blockDim.x)
        g_deginv[i] = 1.0f / (float)max(g_deg[i], 1);
}

// ---------------- edge scatter-add: agg[dst] += feat[src] ---------------------
// One warp processes 32 edges per chunk: coalesced int32 index loads, then
// broadcast via shfl; each lane moves one float4 of the 128-float row.
// Vector reduction (red.global.add.v4.f32) quarters the atomic op count.
__global__ void k_scatter(const float4* __restrict__ feat_ext, int use_h1,
                          const int* __restrict__ ei) {
    const float4* feat = use_h1 ? (const float4*)g_h1 : feat_ext;
    int gw   = (blockIdx.x * blockDim.x + threadIdx.x) >> 5;
    int lane = threadIdx.x & 31;
    int nw   = (gridDim.x * blockDim.x) >> 5;
    const int* srcp = ei;
    const int* dstp = ei + kE;
    for (int base = gw * 32; base < kE; base += nw * 32) {
        int e = base + lane;
        int s = 0, d = 0;
        if (e < kE) { s = srcp[e]; d = dstp[e]; }
        int cnt = min(32, kE - base);
        for (int i = 0; i < cnt; i++) {
            int ss = __shfl_sync(0xffffffffu, s, i);
            int dd = __shfl_sync(0xffffffffu, d, i);
            float4 v = __ldg(&feat[ss * 32 + lane]);
            float* p = (float*)(g_agg + dd * 32 + lane);
            asm volatile("red.global.add.v4.f32 [%0], {%1, %2, %3, %4};"
                         :: "l"(p), "f"(v.x), "f"(v.y), "f"(v.z), "f"(v.w)
                         : "memory");
        }
    }
}

// ---------------- fused SAGE layer --------------------------------------------
// out_row = relu( (agg_row * deginv) @ Wl + b + x_row @ Wr )
// Both weights live in SMEM (128 KB). Each warp processes 2 rows at a time;
// each lane owns 4 output columns (2 f32x2 accumulators per row).
// Row features are staged in SMEM pre-duplicated as f32x2 pairs so the inner
// loop is pure LDS.64 + fma.rn.f32x2 (8 independent chains per k-step).
// POOL=true fuses the readout: s = dot(h2_row, Wfc); gacc[batch[r]] += s,
// so h2 is never materialized in global memory.
#define ROWS_PER_WARP 2
template <bool POOL>
__global__ void __launch_bounds__(256, 1)
k_layer(const float4* __restrict__ xin_ext, int use_h1,
        const float* __restrict__ Wl,
        const float* __restrict__ bias,
        const float* __restrict__ Wr,
        const int* __restrict__ batch,
        const float* __restrict__ Wfc) {
    extern __shared__ float smem[];
    float* Wl_s = smem;                 // 16384 floats = 64 KB
    float* Wr_s = smem + 16384;         // 64 KB
    // per-warp staging: ROWS_PER_WARP rows * 128 k * 2 (a,x) ull = 4 KB/warp
    unsigned long long* stage = (unsigned long long*)(smem + 32768);

    const float4* xin = use_h1 ? (const float4*)g_h1 : xin_ext;

    {   // cooperative weight load ([k][n] row-major, same as global)
        const float4* wl4 = (const float4*)Wl;
        const float4* wr4 = (const float4*)Wr;
        float4* sl = (float4*)Wl_s;
        float4* sr = (float4*)Wr_s;
        for (int i = threadIdx.x; i < 4096; i += blockDim.x) {
            sl[i] = wl4[i];
            sr[i] = wr4[i];
        }
    }
    __syncthreads();

    int warp = threadIdx.x >> 5, lane = threadIdx.x & 31;
    unsigned long long* st_a = stage + warp * (ROWS_PER_WARP * 256);
    unsigned long long* st_x = st_a + ROWS_PER_WARP * 128;
    const unsigned long long* wl2 = (const unsigned long long*)Wl_s;
    const unsigned long long* wr2 = (const unsigned long long*)Wr_s;

    float4 bv = ((const float4*)bias)[lane];
    unsigned long long b01 = pack2(bv.x, bv.y);
    unsigned long long b23 = pack2(bv.z, bv.w);
    float4 wfc4 = make_float4(0.f, 0.f, 0.f, 0.f);
    if (POOL) wfc4 = ((const float4*)Wfc)[lane];

    int gw = blockIdx.x * (blockDim.x >> 5) + warp;
    int nw = gridDim.x * (blockDim.x >> 5);
    int ngroups = (kN + ROWS_PER_WARP - 1) / ROWS_PER_WARP;

    for (int q = gw; q < ngroups; q += nw) {
        int r0 = q * ROWS_PER_WARP;
        __syncwarp();
#pragma unroll
        for (int j = 0; j < ROWS_PER_WARP; j++) {
            int r = r0 + j;
            float4 a, x;
            if (r < kN) {
                float di = g_deginv[r];
                a = g_agg[r * 32 + lane];
                a.x *= di; a.y *= di; a.z *= di; a.w *= di;
                x = xin[r * 32 + lane];
            } else {
                a = make_float4(0.f, 0.f, 0.f, 0.f);
                x = a;
            }
            st_a[j * 128 + lane * 4 + 0] = pack2(a.x, a.x);
            st_a[j * 128 + lane * 4 + 1] = pack2(a.y, a.y);
            st_a[j * 128 + lane * 4 + 2] = pack2(a.z, a.z);
            st_a[j * 128 + lane * 4 + 3] = pack2(a.w, a.w);
            st_x[j * 128 + lane * 4 + 0] = pack2(x.x, x.x);
            st_x[j * 128 + lane * 4 + 1] = pack2(x.y, x.y);
            st_x[j * 128 + lane * 4 + 2] = pack2(x.z, x.z);
            st_x[j * 128 + lane * 4 + 3] = pack2(x.w, x.w);
        }
        __syncwarp();

        unsigned long long acc0[ROWS_PER_WARP], acc1[ROWS_PER_WARP];
#pragma unroll
        for (int j = 0; j < ROWS_PER_WARP; j++) { acc0[j] = b01; acc1[j] = b23; }

#pragma unroll 8
        for (int k = 0; k < 128; k++) {
            unsigned long long wl01 = wl2[k * 64 + lane * 2];
            unsigned long long wl23 = wl2[k * 64 + lane * 2 + 1];
            unsigned long long wr01 = wr2[k * 64 + lane * 2];
            unsigned long long wr23 = wr2[k * 64 + lane * 2 + 1];
#pragma unroll
            for (int j = 0; j < ROWS_PER_WARP; j++) {
                unsigned long long av = st_a[j * 128 + k];
                unsigned long long xv = st_x[j * 128 + k];
                acc0[j] = fma2(av, wl01, acc0[j]);
                acc1[j] = fma2(av, wl23, acc1[j]);
                acc0[j] = fma2(xv, wr01, acc0[j]);
                acc1[j] = fma2(xv, wr23, acc1[j]);
            }
        }

#pragma unroll
        for (int j = 0; j < ROWS_PER_WARP; j++) {
            int r = r0 + j;
            if (r >= kN) continue;
            float o0, o1, o2, o3;
            unpack2(acc0[j], o0, o1);
            unpack2(acc1[j], o2, o3);
            o0 = fmaxf(o0, 0.f);
            o1 = fmaxf(o1, 0.f);
            o2 = fmaxf(o2, 0.f);
            o3 = fmaxf(o3, 0.f);
            if (!POOL) {
                g_h1[r * 32 + lane] = make_float4(o0, o1, o2, o3);
            } else {
                float s = o0 * wfc4.x + o1 * wfc4.y + o2 * wfc4.z + o3 * wfc4.w;
#pragma unroll
                for (int off = 16; off; off >>= 1)
                    s += __shfl_xor_sync(0xffffffffu, s, off);
                if (lane == 0) atomicAdd(&g_gacc[batch[r]], s);
            }
        }
    }
}

__global__ void k_final(const float* __restrict__ bfc, float* __restrict__ out) {
    int g = threadIdx.x;
    if (g < kG) out[g] = g_gacc[g] / (float)max(g_gcnt[g], 1) + bfc[0];
}

// ---------------- entry point --------------------------------------------------
extern "C" void kernel_launch(void* const* d_in, const int* in_sizes, int n_in,
                              void* d_out, int out_size) {
    const float4* x     = (const float4*)d_in[0];
    const int*    ei    = (const int*)d_in[1];    // int32 (JAX x64 disabled)
    const int*    batch = (const int*)d_in[2];    // int32
    const float*  W1l   = (const float*)d_in[3];
    const float*  b1    = (const float*)d_in[4];
    const float*  W1r   = (const float*)d_in[5];
    const float*  W2l   = (const float*)d_in[6];
    const float*  b2    = (const float*)d_in[7];
    const float*  W2r   = (const float*)d_in[8];
    const float*  Wfc   = (const float*)d_in[9];
    const float*  bfc   = (const float*)d_in[10];
    float*        out   = (float*)d_out;

    // 64KB Wl + 64KB Wr + 8 warps * 4KB staging = 160 KB dynamic smem
    const int smem = 2 * 65536 + 8 * (ROWS_PER_WARP * 256) * 8;
    static int attr_done = 0;
    if (!attr_done) {
        cudaFuncSetAttribute(k_layer<false>,
                             cudaFuncAttributeMaxDynamicSharedMemorySize, smem);
        cudaFuncSetAttribute(k_layer<true>,
                             cudaFuncAttributeMaxDynamicSharedMemorySize, smem);
        attr_done = 1;
    }

    k_zero_agg<<<1024, 256>>>();
    k_zero_misc<<<512, 256>>>();
    k_count<<<512, 256>>>(ei, batch);
    k_deginv<<<256, 256>>>();

    // Layer 1
    k_scatter<<<592, 256>>>(x, 0, ei);
    k_layer<false><<<296, 256, smem>>>(x, 0, W1l, b1, W1r, batch, Wfc);

    // Layer 2 (+ fused global-mean-pool readout)
    k_zero_agg<<<1024, 256>>>();
    k_scatter<<<592, 256>>>(x, 1, ei);
    k_layer<true><<<296, 256, smem>>>(x, 1, W2l, b2, W2r, batch, Wfc);

    k_final<<<1, 256>>>(bfc, out);
}

// round 5
// speedup vs baseline: 1.4500x; 1.4500x over previous
#include <cuda_runtime.h>

// Problem constants (fixed by the dataset)
#define kN 100000
#define kE 1600000
#define kG 256
// HID = 128 features = 32 float4 per row

// ---------------- scratch (static device allocations; no cudaMalloc) ----------
__device__ float4 g_agg[kN * 32];   // 51.2 MB  mean-aggregated features
__device__ float4 g_h1 [kN * 32];   // 51.2 MB  layer-1 activations
__device__ int    g_deg[kN];
__device__ int    g_rowptr[kN + 1];
__device__ int    g_cursor[kN];
__device__ int    g_csr[kE];        // 6.4 MB   src indices grouped by dst
__device__ int    g_gcnt[kG];
__device__ float  g_gacc[kG];

// ---------------- f32x2 packed-math helpers (Blackwell) -----------------------
__device__ __forceinline__ unsigned long long pack2(float a, float b) {
    unsigned long long r;
    asm("mov.b64 %0, {%1, %2};" : "=l"(r) : "f"(a), "f"(b));
    return r;
}
__device__ __forceinline__ void unpack2(unsigned long long v, float &a, float &b) {
    asm("mov.b64 {%0, %1}, %2;" : "=f"(a), "=f"(b) : "l"(v));
}
__device__ __forceinline__ unsigned long long fma2(unsigned long long a,
                                                   unsigned long long b,
                                                   unsigned long long c) {
    unsigned long long d;
    asm("fma.rn.f32x2 %0, %1, %2, %3;" : "=l"(d) : "l"(a), "l"(b), "l"(c));
    return d;
}

// ---------------- CSR build ----------------------------------------------------
__global__ void k_zero_misc() {
    int i = blockIdx.x * blockDim.x + threadIdx.x;
    int stride = gridDim.x * blockDim.x;
    for (int j = i; j < kN; j += stride) g_deg[j] = 0;
    if (i < kG) { g_gcnt[i] = 0; g_gacc[i] = 0.f; }
}

// edge_index / batch are int32 on the wire (JAX x64 disabled).
__global__ void k_count(const int* __restrict__ ei,
                        const int* __restrict__ batch) {
    int t = blockIdx.x * blockDim.x + threadIdx.x;
    int stride = gridDim.x * blockDim.x;
    const int* dstp = ei + kE;
    for (int e = t; e < kE; e += stride) atomicAdd(&g_deg[dstp[e]], 1);
    for (int i = t; i < kN; i += stride) atomicAdd(&g_gcnt[batch[i]], 1);
}

// single-block exclusive scan of g_deg -> g_rowptr (and cursor copy)
__global__ void k_scan() {
    __shared__ int wsums[32];
    __shared__ int sbase;
    int tid = threadIdx.x, lane = tid & 31, w = tid >> 5;
    if (tid == 0) sbase = 0;
    __syncthreads();
    for (int base = 0; base < kN; base += 1024) {
        int i = base + tid;
        int v = (i < kN) ? g_deg[i] : 0;
        int x = v;
#pragma unroll
        for (int off = 1; off < 32; off <<= 1) {
            int y = __shfl_up_sync(0xffffffffu, x, off);
            if (lane >= off) x += y;
        }
        if (lane == 31) wsums[w] = x;
        __syncthreads();
        if (w == 0) {
            int s = wsums[lane];
#pragma unroll
            for (int off = 1; off < 32; off <<= 1) {
                int y = __shfl_up_sync(0xffffffffu, s, off);
                if (lane >= off) s += y;
            }
            wsums[lane] = s;
        }
        __syncthreads();
        int woff = (w > 0) ? wsums[w - 1] : 0;
        int incl = sbase + woff + x;           // inclusive prefix for index i
        if (i < kN) {
            g_rowptr[i + 1] = incl;
            g_cursor[i]     = incl - v;        // exclusive prefix
        }
        __syncthreads();
        if (tid == 1023) sbase = incl;         // chunk-carry
        __syncthreads();
    }
    if (tid == 0) g_rowptr[0] = 0;
}

__global__ void k_fill(const int* __restrict__ ei) {
    int t = blockIdx.x * blockDim.x + threadIdx.x;
    int stride = gridDim.x * blockDim.x;
    const int* srcp = ei;
    const int* dstp = ei + kE;
    for (int e = t; e < kE; e += stride) {
        int pos = atomicAdd(&g_cursor[dstp[e]], 1);
        g_csr[pos] = srcp[e];
    }
}

// ---------------- gather-based mean aggregation -------------------------------
// One warp per node: lanes cooperatively load 32 edge indices (coalesced),
// broadcast via shfl, each lane accumulates its own float4 column slice.
// Two accumulators (edge parity) break the FADD dependency chain.
// Degree normalization fused in; result is a plain streaming write (no atomics,
// no pre-zeroing of g_agg needed).
__global__ void k_gather(const float4* __restrict__ feat_ext, int use_h1) {
    const float4* feat = use_h1 ? (const float4*)g_h1 : feat_ext;
    int gw   = (blockIdx.x * blockDim.x + threadIdx.x) >> 5;
    int lane = threadIdx.x & 31;
    int nw   = (gridDim.x * blockDim.x) >> 5;
    for (int node = gw; node < kN; node += nw) {
        int beg = g_rowptr[node];
        int end = g_rowptr[node + 1];
        float4 a0 = make_float4(0.f, 0.f, 0.f, 0.f);
        float4 a1 = make_float4(0.f, 0.f, 0.f, 0.f);
        for (int b = beg; b < end; b += 32) {
            int e = b + lane;
            int idx = (e < end) ? g_csr[e] : 0;
            int cnt = min(32, end - b);
            for (int i = 0; i < cnt - 1; i += 2) {
                int s0 = __shfl_sync(0xffffffffu, idx, i);
                int s1 = __shfl_sync(0xffffffffu, idx, i + 1);
                float4 v0 = __ldg(&feat[s0 * 32 + lane]);
                float4 v1 = __ldg(&feat[s1 * 32 + lane]);
                a0.x += v0.x; a0.y += v0.y; a0.z += v0.z; a0.w += v0.w;
                a1.x += v1.x; a1.y += v1.y; a1.z += v1.z; a1.w += v1.w;
            }
            if (cnt & 1) {
                int s0 = __shfl_sync(0xffffffffu, idx, cnt - 1);
                float4 v0 = __ldg(&feat[s0 * 32 + lane]);
                a0.x += v0.x; a0.y += v0.y; a0.z += v0.z; a0.w += v0.w;
            }
        }
        float di = 1.0f / (float)max(end - beg, 1);
        a0.x = (a0.x + a1.x) * di;
        a0.y = (a0.y + a1.y) * di;
        a0.z = (a0.z + a1.z) * di;
        a0.w = (a0.w + a1.w) * di;
        g_agg[node * 32 + lane] = a0;
    }
}

// ---------------- fused SAGE layer --------------------------------------------
// out_row = relu( agg_row @ Wl + b + x_row @ Wr )   (agg pre-scaled by 1/deg)
// Both weights live in SMEM (128 KB). Each warp processes 4 rows; each lane
// owns 4 output columns (2 f32x2 accumulators per row). Row features are
// staged in SMEM pre-duplicated as f32x2 pairs (broadcast LDS.64), so the
// weight LDS traffic (the crossbar-binding term) is amortized over 4 rows.
// POOL=true fuses the readout: s = dot(h2_row, Wfc); gacc[batch[r]] += s.
#define ROWS_PER_WARP 4
template <bool POOL>
__global__ void __launch_bounds__(256, 1)
k_layer(const float4* __restrict__ xin_ext, int use_h1,
        const float* __restrict__ Wl,
        const float* __restrict__ bias,
        const float* __restrict__ Wr,
        const int* __restrict__ batch,
        const float* __restrict__ Wfc) {
    extern __shared__ float smem[];
    float* Wl_s = smem;                 // 64 KB
    float* Wr_s = smem + 16384;         // 64 KB
    unsigned long long* stage = (unsigned long long*)(smem + 32768); // 8w * 8KB

    const float4* xin = use_h1 ? (const float4*)g_h1 : xin_ext;

    {   // cooperative weight load ([k][n] row-major, same as global)
        const float4* wl4 = (const float4*)Wl;
        const float4* wr4 = (const float4*)Wr;
        float4* sl = (float4*)Wl_s;
        float4* sr = (float4*)Wr_s;
        for (int i = threadIdx.x; i < 4096; i += blockDim.x) {
            sl[i] = wl4[i];
            sr[i] = wr4[i];
        }
    }
    __syncthreads();

    int warp = threadIdx.x >> 5, lane = threadIdx.x & 31;
    unsigned long long* st_a = stage + warp * (ROWS_PER_WARP * 256);
    unsigned long long* st_x = st_a + ROWS_PER_WARP * 128;
    const unsigned long long* wl2 = (const unsigned long long*)Wl_s;
    const unsigned long long* wr2 = (const unsigned long long*)Wr_s;

    float4 bv = ((const float4*)bias)[lane];
    unsigned long long b01 = pack2(bv.x, bv.y);
    unsigned long long b23 = pack2(bv.z, bv.w);
    float4 wfc4 = make_float4(0.f, 0.f, 0.f, 0.f);
    if (POOL) wfc4 = ((const float4*)Wfc)[lane];

    int gw = blockIdx.x * (blockDim.x >> 5) + warp;
    int nw = gridDim.x * (blockDim.x >> 5);
    int ngroups = (kN + ROWS_PER_WARP - 1) / ROWS_PER_WARP;

    for (int q = gw; q < ngroups; q += nw) {
        int r0 = q * ROWS_PER_WARP;
        __syncwarp();
#pragma unroll
        for (int j = 0; j < ROWS_PER_WARP; j++) {
            int r = r0 + j;
            float4 a, x;
            if (r < kN) {
                a = g_agg[r * 32 + lane];
                x = xin[r * 32 + lane];
            } else {
                a = make_float4(0.f, 0.f, 0.f, 0.f);
                x = a;
            }
            st_a[j * 128 + lane * 4 + 0] = pack2(a.x, a.x);
            st_a[j * 128 + lane * 4 + 1] = pack2(a.y, a.y);
            st_a[j * 128 + lane * 4 + 2] = pack2(a.z, a.z);
            st_a[j * 128 + lane * 4 + 3] = pack2(a.w, a.w);
            st_x[j * 128 + lane * 4 + 0] = pack2(x.x, x.x);
            st_x[j * 128 + lane * 4 + 1] = pack2(x.y, x.y);
            st_x[j * 128 + lane * 4 + 2] = pack2(x.z, x.z);
            st_x[j * 128 + lane * 4 + 3] = pack2(x.w, x.w);
        }
        __syncwarp();

        unsigned long long acc0[ROWS_PER_WARP], acc1[ROWS_PER_WARP];
#pragma unroll
        for (int j = 0; j < ROWS_PER_WARP; j++) { acc0[j] = b01; acc1[j] = b23; }

#pragma unroll 4
        for (int k = 0; k < 128; k++) {
            unsigned long long wl01 = wl2[k * 64 + lane * 2];
            unsigned long long wl23 = wl2[k * 64 + lane * 2 + 1];
            unsigned long long wr01 = wr2[k * 64 + lane * 2];
            unsigned long long wr23 = wr2[k * 64 + lane * 2 + 1];
#pragma unroll
            for (int j = 0; j < ROWS_PER_WARP; j++) {
                unsigned long long av = st_a[j * 128 + k];
                unsigned long long xv = st_x[j * 128 + k];
                acc0[j] = fma2(av, wl01, acc0[j]);
                acc1[j] = fma2(av, wl23, acc1[j]);
                acc0[j] = fma2(xv, wr01, acc0[j]);
                acc1[j] = fma2(xv, wr23, acc1[j]);
            }
        }

#pragma unroll
        for (int j = 0; j < ROWS_PER_WARP; j++) {
            int r = r0 + j;
            if (r >= kN) continue;
            float o0, o1, o2, o3;
            unpack2(acc0[j], o0, o1);
            unpack2(acc1[j], o2, o3);
            o0 = fmaxf(o0, 0.f);
            o1 = fmaxf(o1, 0.f);
            o2 = fmaxf(o2, 0.f);
            o3 = fmaxf(o3, 0.f);
            if (!POOL) {
                g_h1[r * 32 + lane] = make_float4(o0, o1, o2, o3);
            } else {
                float s = o0 * wfc4.x + o1 * wfc4.y + o2 * wfc4.z + o3 * wfc4.w;
#pragma unroll
                for (int off = 16; off; off >>= 1)
                    s += __shfl_xor_sync(0xffffffffu, s, off);
                if (lane == 0) atomicAdd(&g_gacc[batch[r]], s);
            }
        }
    }
}

__global__ void k_final(const float* __restrict__ bfc, float* __restrict__ out) {
    int g = threadIdx.x;
    if (g < kG) out[g] = g_gacc[g] / (float)max(g_gcnt[g], 1) + bfc[0];
}

// ---------------- entry point --------------------------------------------------
extern "C" void kernel_launch(void* const* d_in, const int* in_sizes, int n_in,
                              void* d_out, int out_size) {
    const float4* x     = (const float4*)d_in[0];
    const int*    ei    = (const int*)d_in[1];    // int32 (JAX x64 disabled)
    const int*    batch = (const int*)d_in[2];    // int32
    const float*  W1l   = (const float*)d_in[3];
    const float*  b1    = (const float*)d_in[4];
    const float*  W1r   = (const float*)d_in[5];
    const float*  W2l   = (const float*)d_in[6];
    const float*  b2    = (const float*)d_in[7];
    const float*  W2r   = (const float*)d_in[8];
    const float*  Wfc   = (const float*)d_in[9];
    const float*  bfc   = (const float*)d_in[10];
    float*        out   = (float*)d_out;

    // 64KB Wl + 64KB Wr + 8 warps * 8KB staging = 192 KB dynamic smem
    const int smem = 2 * 65536 + 8 * (ROWS_PER_WARP * 256) * 8;
    static int attr_done = 0;
    if (!attr_done) {
        cudaFuncSetAttribute(k_layer<false>,
                             cudaFuncAttributeMaxDynamicSharedMemorySize, smem);
        cudaFuncSetAttribute(k_layer<true>,
                             cudaFuncAttributeMaxDynamicSharedMemorySize, smem);
        attr_done = 1;
    }

    // CSR build (per call; deterministic up to fp-sum order)
    k_zero_misc<<<512, 256>>>();
    k_count<<<512, 256>>>(ei, batch);
    k_scan<<<1, 1024>>>();
    k_fill<<<512, 256>>>(ei);

    // Layer 1
    k_gather<<<1024, 256>>>(x, 0);
    k_layer<false><<<148, 256, smem>>>(x, 0, W1l, b1, W1r, batch, Wfc);

    // Layer 2 (+ fused global-mean-pool readout)
    k_gather<<<1024, 256>>>(x, 1);
    k_layer<true><<<148, 256, smem>>>(x, 1, W2l, b2, W2r, batch, Wfc);

    k_final<<<1, 256>>>(bfc, out);
}